// round 6
// baseline (speedup 1.0000x reference)
#include <cuda_runtime.h>
#include <cuda_fp16.h>
#include <cstdint>

#define NTOK 8192
#define DIN  512
#define DHEAD 256
#define NSPLIT 2
#define BM 128
#define BN 64
#define JBLOCKS (NTOK / NSPLIT / BN)   // 64

// ---------------- scratch ----------------
__device__ __half g_Qh[NTOK * DHEAD];        // fp16, pre-scaled by 1/16
__device__ __half g_Kh[NTOK * DHEAD];        // fp16
__device__ __half g_Vt[DHEAD * NTOK];        // V transposed [d][tok], fp16
__device__ float  g_Op[NSPLIT][NTOK][DHEAD];
__device__ float  g_ls[NSPLIT][NTOK];

// ---------------- helpers ----------------
__device__ __forceinline__ uint32_t smem_u32(const void* p) {
    uint32_t a;
    asm("{ .reg .u64 t; cvta.to.shared.u64 t, %1; cvt.u32.u64 %0, t; }" : "=r"(a) : "l"(p));
    return a;
}
__device__ __forceinline__ void cp16(uint32_t dst, const void* src) {
    asm volatile("cp.async.cg.shared.global [%0], [%1], 16;" :: "r"(dst), "l"(src));
}
#define CP_COMMIT() asm volatile("cp.async.commit_group;" ::: "memory")
#define CP_WAIT(n)  asm volatile("cp.async.wait_group %0;" :: "n"(n) : "memory")

__device__ __forceinline__ void mma_f16(float& c0, float& c1, float& c2, float& c3,
                                        unsigned a0, unsigned a1, unsigned a2, unsigned a3,
                                        unsigned b0, unsigned b1) {
    asm volatile(
        "mma.sync.aligned.m16n8k16.row.col.f32.f16.f16.f32 "
        "{%0,%1,%2,%3}, {%4,%5,%6,%7}, {%8,%9}, {%0,%1,%2,%3};"
        : "+f"(c0), "+f"(c1), "+f"(c2), "+f"(c3)
        : "r"(a0), "r"(a1), "r"(a2), "r"(a3), "r"(b0), "r"(b1));
}

// ---------------- kernel 1: QKV projection, fp16 x2 (split-A), fp16 outputs ----------------
// C = feat[8192,512] @ W[512,256]. A split hi/lo fp16; B single-rounded fp16.
__global__ __launch_bounds__(256) void proj_kernel(const float* __restrict__ feat,
                                                   const float* __restrict__ Wq,
                                                   const float* __restrict__ Wk,
                                                   const float* __restrict__ Wv) {
    __shared__ __half2 As[2][128][8];   // [hi/lo][row][k2 ^ (row&7)]
    __shared__ __half2 Bs[128][8];      // [col][k2 ^ (col&7)]; pairs (B[2k][n],B[2k+1][n])

    const int tid = threadIdx.x;
    const int w = tid >> 5, lane = tid & 31, g = lane >> 2, t = lane & 3;
    const int wm = w >> 1, wn = w & 1;
    const int m0 = blockIdx.x * 128;
    const int n0 = blockIdx.y * 128;
    const int mat = blockIdx.z;
    const float* __restrict__ W = (mat == 0) ? Wq : ((mat == 1) ? Wk : Wv);

    float acc[2][8][4];
#pragma unroll
    for (int mt = 0; mt < 2; mt++)
#pragma unroll
        for (int nt = 0; nt < 8; nt++)
#pragma unroll
            for (int j = 0; j < 4; j++) acc[mt][nt][j] = 0.f;

    for (int kb = 0; kb < DIN; kb += 16) {
        // A tile [128][16] -> hi/lo half2 pairs
#pragma unroll
        for (int i = 0; i < 2; i++) {
            int e = tid + 256 * i;
            int r = e >> 2, c = (e & 3) << 2;   // c = 0,4,8,12
            float4 v = *(const float4*)&feat[(size_t)(m0 + r) * DIN + kb + c];
            __half hx = __float2half_rn(v.x), hy = __float2half_rn(v.y);
            __half hz = __float2half_rn(v.z), hw = __float2half_rn(v.w);
            __half lx = __float2half_rn(v.x - __half2float(hx));
            __half ly = __float2half_rn(v.y - __half2float(hy));
            __half lz = __float2half_rn(v.z - __half2float(hz));
            __half lw = __float2half_rn(v.w - __half2float(hw));
            int p0 = c >> 1, p1 = p0 + 1, rm = r & 7;
            As[0][r][p0 ^ rm] = __halves2half2(hx, hy);
            As[0][r][p1 ^ rm] = __halves2half2(hz, hw);
            As[1][r][p0 ^ rm] = __halves2half2(lx, ly);
            As[1][r][p1 ^ rm] = __halves2half2(lz, lw);
        }
        // B tile [16][128] -> col-major k-pair half2
#pragma unroll
        for (int i = 0; i < 4; i++) {
            int idx = tid + 256 * i;
            int n = idx & 127, k2 = idx >> 7;    // k2 in 0..7
            float b0 = W[(size_t)(kb + 2 * k2) * DHEAD + n0 + n];
            float b1 = W[(size_t)(kb + 2 * k2 + 1) * DHEAD + n0 + n];
            Bs[n][k2 ^ (n & 7)] = __halves2half2(__float2half_rn(b0), __float2half_rn(b1));
        }
        __syncthreads();

        unsigned b[8][2];
#pragma unroll
        for (int nt = 0; nt < 8; nt++) {
            int n = 64 * wn + 8 * nt + g, nm = n & 7;
            b[nt][0] = *(const unsigned*)&Bs[n][t ^ nm];
            b[nt][1] = *(const unsigned*)&Bs[n][(t + 4) ^ nm];
        }
#pragma unroll
        for (int sp = 0; sp < 2; sp++) {
#pragma unroll
            for (int mt = 0; mt < 2; mt++) {
                int r = 32 * wm + 16 * mt + g, rm = r & 7;
                unsigned a0 = *(const unsigned*)&As[sp][r][t ^ rm];
                unsigned a1 = *(const unsigned*)&As[sp][r + 8][t ^ rm];
                unsigned a2 = *(const unsigned*)&As[sp][r][(t + 4) ^ rm];
                unsigned a3 = *(const unsigned*)&As[sp][r + 8][(t + 4) ^ rm];
#pragma unroll
                for (int nt = 0; nt < 8; nt++)
                    mma_f16(acc[mt][nt][0], acc[mt][nt][1], acc[mt][nt][2], acc[mt][nt][3],
                            a0, a1, a2, a3, b[nt][0], b[nt][1]);
            }
        }
        __syncthreads();
    }

    const float scale = (mat == 0) ? 0.0625f : 1.0f;  // fold 1/sqrt(256) into Q
#pragma unroll
    for (int mt = 0; mt < 2; mt++) {
        int r = m0 + 32 * wm + 16 * mt + g;
#pragma unroll
        for (int nt = 0; nt < 8; nt++) {
            int col = n0 + 64 * wn + 8 * nt + 2 * t;
            __half h00 = __float2half_rn(acc[mt][nt][0] * scale);
            __half h01 = __float2half_rn(acc[mt][nt][1] * scale);
            __half h10 = __float2half_rn(acc[mt][nt][2] * scale);
            __half h11 = __float2half_rn(acc[mt][nt][3] * scale);
            if (mat == 2) {
                g_Vt[(size_t)col * NTOK + r] = h00;
                g_Vt[(size_t)(col + 1) * NTOK + r] = h01;
                g_Vt[(size_t)col * NTOK + r + 8] = h10;
                g_Vt[(size_t)(col + 1) * NTOK + r + 8] = h11;
            } else {
                __half* dst = (mat == 0) ? g_Qh : g_Kh;
                *(__half2*)&dst[(size_t)r * DHEAD + col] = __halves2half2(h00, h01);
                *(__half2*)&dst[(size_t)(r + 8) * DHEAD + col] = __halves2half2(h10, h11);
            }
        }
    }
}

// ---------------- kernel 2: pipelined fp16 attention ----------------
// SMEM layout (bytes):
#define SMO_Q   0u        // [128][256] half, row stride 512, swizzled
#define SMO_K0  65536u    // [64][256] half
#define SMO_K1  98304u
#define SMO_V   131072u   // [256][64] half (V^T)
#define SMO_P   163840u   // [128] rows x 144B (64 half + 8 pad), NOT swizzled
#define SMO_L   182272u   // 256 floats
#define SMEM_DYN (182272u + 1024u + 768u)

__global__ __launch_bounds__(256, 1) void attn_kernel(const float* __restrict__ cnt) {
    extern __shared__ char sm[];
    const uint32_t sb = smem_u32(sm);

    const int tid = threadIdx.x, w = tid >> 5, lane = tid & 31;
    const int g = lane >> 2, t = lane & 3;
    const int wm = w & 3, wh = w >> 2;     // 4 m-warps x 2 n/d-half warps
    const int m0 = blockIdx.x * BM;
    const int sp = blockIdx.y;
    const int jb0 = sp * (NTOK / NSPLIT);

    // ---- prologue: Q tile + K_0 via cp.async (group 0) ----
#pragma unroll
    for (int i = 0; i < 16; i++) {
        int e = tid + 256 * i;
        int r = e >> 5, blk = e & 31;
        uint32_t d = sb + SMO_Q + (uint32_t)r * 512u + (uint32_t)(((4 * blk) ^ ((r & 7) << 2)) << 2);
        cp16(d, &g_Qh[(size_t)(m0 + r) * DHEAD + 8 * blk]);
    }
#pragma unroll
    for (int i = 0; i < 8; i++) {
        int e = tid + 256 * i;
        int r = e >> 5, blk = e & 31;
        uint32_t d = sb + SMO_K0 + (uint32_t)r * 512u + (uint32_t)(((4 * blk) ^ ((r & 7) << 2)) << 2);
        cp16(d, &g_Kh[(size_t)(jb0 + r) * DHEAD + 8 * blk]);
    }
    CP_COMMIT();

    float O[2][16][4];
#pragma unroll
    for (int mt = 0; mt < 2; mt++)
#pragma unroll
        for (int nt = 0; nt < 16; nt++)
#pragma unroll
            for (int q = 0; q < 4; q++) O[mt][nt][q] = 0.f;
    float lA[2] = {0.f, 0.f}, lB[2] = {0.f, 0.f};

    const int rA0 = 32 * wm + g, rB0 = rA0 + 8;   // mt=0 rows; mt=1 adds 16

    for (int j = 0; j < JBLOCKS; j++) {
        const int jb = jb0 + j * BN;

        // ---- prefetch cnt tile slice straight to registers (consumed in epilogue) ----
        float2 cA[2][4], cB[2][4];
#pragma unroll
        for (int mt = 0; mt < 2; mt++)
#pragma unroll
            for (int nt = 0; nt < 4; nt++) {
                const float* base =
                    &cnt[(size_t)(m0 + rA0 + 16 * mt) * NTOK + jb + 32 * wh + 8 * nt + 2 * t];
                cA[mt][nt] = *(const float2*)base;
                cB[mt][nt] = *(const float2*)(base + (size_t)8 * NTOK);
            }

        __syncthreads();   // prev AV done with V/P; K[(j+1)&1] free

        // ---- issue V_j (group) ----
#pragma unroll
        for (int i = 0; i < 8; i++) {
            int e = tid + 256 * i;
            int dd = e >> 3, blk = e & 7;
            uint32_t d = sb + SMO_V + (uint32_t)dd * 128u + (uint32_t)(((4 * blk) ^ ((dd & 7) << 2)) << 2);
            cp16(d, &g_Vt[(size_t)dd * NTOK + jb + 8 * blk]);
        }
        CP_COMMIT();

        // ---- issue K_{j+1} (own group; empty group on last iter) ----
        if (j + 1 < JBLOCKS) {
            uint32_t kb = ((j + 1) & 1) ? SMO_K1 : SMO_K0;
#pragma unroll
            for (int i = 0; i < 8; i++) {
                int e = tid + 256 * i;
                int r = e >> 5, blk = e & 31;
                uint32_t d = sb + kb + (uint32_t)r * 512u + (uint32_t)(((4 * blk) ^ ((r & 7) << 2)) << 2);
                cp16(d, &g_Kh[(size_t)(jb + BN + r) * DHEAD + 8 * blk]);
            }
        }
        CP_COMMIT();

        CP_WAIT(2);        // K_j (and Q on j=0) complete
        __syncthreads();

        // ---- QK_j : warp computes S[32 rows x 32 cols], k = 256 ----
        const char* Ks = sm + ((j & 1) ? SMO_K1 : SMO_K0);
        const char* Qs = sm + SMO_Q;
        float S[2][4][4];
#pragma unroll
        for (int mt = 0; mt < 2; mt++)
#pragma unroll
            for (int nt = 0; nt < 4; nt++)
#pragma unroll
                for (int q = 0; q < 4; q++) S[mt][nt][q] = 0.f;

#pragma unroll 4
        for (int s = 0; s < 16; s++) {
            const int i0 = ((8 * s + t) ^ (g << 2)) << 2;
            const int i1 = ((8 * s + t + 4) ^ (g << 2)) << 2;
            unsigned b[4][2];
#pragma unroll
            for (int nt = 0; nt < 4; nt++) {
                int n = 32 * wh + 8 * nt + g;
                b[nt][0] = *(const unsigned*)(Ks + n * 512 + i0);
                b[nt][1] = *(const unsigned*)(Ks + n * 512 + i1);
            }
#pragma unroll
            for (int mt = 0; mt < 2; mt++) {
                int rA = (rA0 + 16 * mt) * 512, rB = (rB0 + 16 * mt) * 512;
                unsigned a0 = *(const unsigned*)(Qs + rA + i0);
                unsigned a1 = *(const unsigned*)(Qs + rB + i0);
                unsigned a2 = *(const unsigned*)(Qs + rA + i1);
                unsigned a3 = *(const unsigned*)(Qs + rB + i1);
#pragma unroll
                for (int nt = 0; nt < 4; nt++)
                    mma_f16(S[mt][nt][0], S[mt][nt][1], S[mt][nt][2], S[mt][nt][3],
                            a0, a1, a2, a3, b[nt][0], b[nt][1]);
            }
        }

        CP_WAIT(1);        // V_j complete (K_{j+1} may still fly)
        __syncthreads();

        // ---- epilogue: P = exp(S) * cnt -> Ps (fp16), accumulate l ----
        char* Ps = sm + SMO_P;
#pragma unroll
        for (int mt = 0; mt < 2; mt++) {
            int rA = rA0 + 16 * mt, rB = rB0 + 16 * mt;
            float sA = 0.f, sB = 0.f;
#pragma unroll
            for (int nt = 0; nt < 4; nt++) {
                float p0 = __expf(S[mt][nt][0]) * cA[mt][nt].x;
                float p1 = __expf(S[mt][nt][1]) * cA[mt][nt].y;
                float p2 = __expf(S[mt][nt][2]) * cB[mt][nt].x;
                float p3 = __expf(S[mt][nt][3]) * cB[mt][nt].y;
                sA += p0 + p1;
                sB += p2 + p3;
                int q = (16 * wh + 4 * nt + t) << 2;
                *(__half2*)(Ps + rA * 144 + q) = __halves2half2(__float2half_rn(p0), __float2half_rn(p1));
                *(__half2*)(Ps + rB * 144 + q) = __halves2half2(__float2half_rn(p2), __float2half_rn(p3));
            }
            sA += __shfl_xor_sync(0xffffffffu, sA, 1);
            sA += __shfl_xor_sync(0xffffffffu, sA, 2);
            sB += __shfl_xor_sync(0xffffffffu, sB, 1);
            sB += __shfl_xor_sync(0xffffffffu, sB, 2);
            lA[mt] += sA;
            lB[mt] += sB;
        }
        __syncthreads();   // P visible to all warps

        // ---- AV_j : O[32 rows x 128 cols(d-half)] += P @ V^T, k = 64 ----
        const char* Vs = sm + SMO_V;
        const char* Psr = sm + SMO_P;
#pragma unroll
        for (int s = 0; s < 4; s++) {
            const int i0 = ((8 * s + t) ^ (g << 2)) << 2;
            const int i1 = ((8 * s + t + 4) ^ (g << 2)) << 2;
            const int p0i = (8 * s + t) << 2;
            const int p1i = (8 * s + t + 4) << 2;
            unsigned bv[16][2];
#pragma unroll
            for (int nt = 0; nt < 16; nt++) {
                int d = 128 * wh + 8 * nt + g;
                bv[nt][0] = *(const unsigned*)(Vs + d * 128 + i0);
                bv[nt][1] = *(const unsigned*)(Vs + d * 128 + i1);
            }
#pragma unroll
            for (int mt = 0; mt < 2; mt++) {
                int rA = (rA0 + 16 * mt) * 144, rB = (rB0 + 16 * mt) * 144;
                unsigned a0 = *(const unsigned*)(Psr + rA + p0i);
                unsigned a1 = *(const unsigned*)(Psr + rB + p0i);
                unsigned a2 = *(const unsigned*)(Psr + rA + p1i);
                unsigned a3 = *(const unsigned*)(Psr + rB + p1i);
#pragma unroll
                for (int nt = 0; nt < 16; nt++)
                    mma_f16(O[mt][nt][0], O[mt][nt][1], O[mt][nt][2], O[mt][nt][3],
                            a0, a1, a2, a3, bv[nt][0], bv[nt][1]);
            }
        }
    }

    // ---- O writeout ----
#pragma unroll
    for (int mt = 0; mt < 2; mt++) {
        int rA = m0 + rA0 + 16 * mt, rB = m0 + rB0 + 16 * mt;
#pragma unroll
        for (int nt = 0; nt < 16; nt++) {
            int col = 128 * wh + 8 * nt + 2 * t;
            *(float2*)&g_Op[sp][rA][col] = make_float2(O[mt][nt][0], O[mt][nt][1]);
            *(float2*)&g_Op[sp][rB][col] = make_float2(O[mt][nt][2], O[mt][nt][3]);
        }
    }

    // ---- l reduce across the two wh warps ----
    float* Lr = (float*)(sm + SMO_L);
    if (t == 0) {
#pragma unroll
        for (int mt = 0; mt < 2; mt++) {
            Lr[wh * 128 + rA0 + 16 * mt] = lA[mt];
            Lr[wh * 128 + rB0 + 16 * mt] = lB[mt];
        }
    }
    __syncthreads();
    if (tid < 128) g_ls[sp][m0 + tid] = Lr[tid] + Lr[128 + tid];
}

// ---------------- kernel 3: combine + ELU ----------------
__global__ __launch_bounds__(256) void combine_kernel(float* __restrict__ out) {
    const int i = blockIdx.x;
    const int d = threadIdx.x;
    float den = g_ls[0][i] + g_ls[1][i];
    float num = g_Op[0][i][d] + g_Op[1][i][d];
    float r = num / den;
    out[(size_t)i * DHEAD + d] = (r > 0.f) ? r : expm1f(r);
}

// ---------------- launch ----------------
extern "C" void kernel_launch(void* const* d_in, const int* in_sizes, int n_in,
                              void* d_out, int out_size) {
    (void)in_sizes; (void)n_in; (void)out_size;
    const float* feat = (const float*)d_in[0];
    const float* cnt = (const float*)d_in[1];
    const float* Wq = (const float*)d_in[2];
    const float* Wk = (const float*)d_in[3];
    const float* Wv = (const float*)d_in[4];

    proj_kernel<<<dim3(NTOK / 128, DHEAD / 128, 3), 256>>>(feat, Wq, Wk, Wv);

    cudaFuncSetAttribute(attn_kernel, cudaFuncAttributeMaxDynamicSharedMemorySize, (int)SMEM_DYN);
    attn_kernel<<<dim3(NTOK / BM, NSPLIT), 256, SMEM_DYN>>>(cnt);

    combine_kernel<<<NTOK, 256>>>((float*)d_out);
}

// round 7
// speedup vs baseline: 1.1705x; 1.1705x over previous
#include <cuda_runtime.h>
#include <cuda_fp16.h>
#include <cstdint>

#define NTOK 8192
#define DIN  512
#define DHEAD 256
#define NSPLIT 2
#define BM 128
#define BN 64
#define JBLOCKS (NTOK / NSPLIT / BN)   // 64

// ---------------- scratch ----------------
__device__ __half g_Qh[NTOK * DHEAD];        // fp16, pre-scaled by 1/16
__device__ __half g_Kh[NTOK * DHEAD];        // fp16
__device__ __half g_Vt[DHEAD * NTOK];        // V transposed [d][tok], fp16
__device__ float  g_Op[NSPLIT][NTOK][DHEAD];
__device__ float  g_ls[NSPLIT][NTOK];

// ---------------- helpers ----------------
__device__ __forceinline__ uint32_t smem_u32(const void* p) {
    uint32_t a;
    asm("{ .reg .u64 t; cvta.to.shared.u64 t, %1; cvt.u32.u64 %0, t; }" : "=r"(a) : "l"(p));
    return a;
}
__device__ __forceinline__ void cp16(uint32_t dst, const void* src) {
    asm volatile("cp.async.cg.shared.global [%0], [%1], 16;" :: "r"(dst), "l"(src));
}
#define CP_COMMIT() asm volatile("cp.async.commit_group;" ::: "memory")
#define CP_WAIT(n)  asm volatile("cp.async.wait_group %0;" :: "n"(n) : "memory")

__device__ __forceinline__ void ldsm4(unsigned& r0, unsigned& r1, unsigned& r2, unsigned& r3,
                                      uint32_t a) {
    asm volatile("ldmatrix.sync.aligned.m8n8.x4.shared.b16 {%0,%1,%2,%3}, [%4];"
                 : "=r"(r0), "=r"(r1), "=r"(r2), "=r"(r3) : "r"(a));
}

__device__ __forceinline__ void mma_f16(float& c0, float& c1, float& c2, float& c3,
                                        unsigned a0, unsigned a1, unsigned a2, unsigned a3,
                                        unsigned b0, unsigned b1) {
    asm volatile(
        "mma.sync.aligned.m16n8k16.row.col.f32.f16.f16.f32 "
        "{%0,%1,%2,%3}, {%4,%5,%6,%7}, {%8,%9}, {%0,%1,%2,%3};"
        : "+f"(c0), "+f"(c1), "+f"(c2), "+f"(c3)
        : "r"(a0), "r"(a1), "r"(a2), "r"(a3), "r"(b0), "r"(b1));
}

// ---------------- kernel 1: QKV projection, fp16 x2 (split-A), fp16 outputs ----------------
__global__ __launch_bounds__(256) void proj_kernel(const float* __restrict__ feat,
                                                   const float* __restrict__ Wq,
                                                   const float* __restrict__ Wk,
                                                   const float* __restrict__ Wv) {
    __shared__ __half2 As[2][128][8];   // [hi/lo][row][k2 ^ (row&7)]
    __shared__ __half2 Bs[128][8];      // [col][k2 ^ (col&7)]

    const int tid = threadIdx.x;
    const int w = tid >> 5, lane = tid & 31, g = lane >> 2, t = lane & 3;
    const int wm = w >> 1, wn = w & 1;
    const int m0 = blockIdx.x * 128;
    const int n0 = blockIdx.y * 128;
    const int mat = blockIdx.z;
    const float* __restrict__ W = (mat == 0) ? Wq : ((mat == 1) ? Wk : Wv);

    float acc[2][8][4];
#pragma unroll
    for (int mt = 0; mt < 2; mt++)
#pragma unroll
        for (int nt = 0; nt < 8; nt++)
#pragma unroll
            for (int j = 0; j < 4; j++) acc[mt][nt][j] = 0.f;

    for (int kb = 0; kb < DIN; kb += 16) {
#pragma unroll
        for (int i = 0; i < 2; i++) {
            int e = tid + 256 * i;
            int r = e >> 2, c = (e & 3) << 2;
            float4 v = *(const float4*)&feat[(size_t)(m0 + r) * DIN + kb + c];
            __half hx = __float2half_rn(v.x), hy = __float2half_rn(v.y);
            __half hz = __float2half_rn(v.z), hw = __float2half_rn(v.w);
            __half lx = __float2half_rn(v.x - __half2float(hx));
            __half ly = __float2half_rn(v.y - __half2float(hy));
            __half lz = __float2half_rn(v.z - __half2float(hz));
            __half lw = __float2half_rn(v.w - __half2float(hw));
            int p0 = c >> 1, p1 = p0 + 1, rm = r & 7;
            As[0][r][p0 ^ rm] = __halves2half2(hx, hy);
            As[0][r][p1 ^ rm] = __halves2half2(hz, hw);
            As[1][r][p0 ^ rm] = __halves2half2(lx, ly);
            As[1][r][p1 ^ rm] = __halves2half2(lz, lw);
        }
#pragma unroll
        for (int i = 0; i < 4; i++) {
            int idx = tid + 256 * i;
            int n = idx & 127, k2 = idx >> 7;
            float b0 = W[(size_t)(kb + 2 * k2) * DHEAD + n0 + n];
            float b1 = W[(size_t)(kb + 2 * k2 + 1) * DHEAD + n0 + n];
            Bs[n][k2 ^ (n & 7)] = __halves2half2(__float2half_rn(b0), __float2half_rn(b1));
        }
        __syncthreads();

        unsigned b[8][2];
#pragma unroll
        for (int nt = 0; nt < 8; nt++) {
            int n = 64 * wn + 8 * nt + g, nm = n & 7;
            b[nt][0] = *(const unsigned*)&Bs[n][t ^ nm];
            b[nt][1] = *(const unsigned*)&Bs[n][(t + 4) ^ nm];
        }
#pragma unroll
        for (int sp = 0; sp < 2; sp++) {
#pragma unroll
            for (int mt = 0; mt < 2; mt++) {
                int r = 32 * wm + 16 * mt + g, rm = r & 7;
                unsigned a0 = *(const unsigned*)&As[sp][r][t ^ rm];
                unsigned a1 = *(const unsigned*)&As[sp][r + 8][t ^ rm];
                unsigned a2 = *(const unsigned*)&As[sp][r][(t + 4) ^ rm];
                unsigned a3 = *(const unsigned*)&As[sp][r + 8][(t + 4) ^ rm];
#pragma unroll
                for (int nt = 0; nt < 8; nt++)
                    mma_f16(acc[mt][nt][0], acc[mt][nt][1], acc[mt][nt][2], acc[mt][nt][3],
                            a0, a1, a2, a3, b[nt][0], b[nt][1]);
            }
        }
        __syncthreads();
    }

    const float scale = (mat == 0) ? 0.0625f : 1.0f;
#pragma unroll
    for (int mt = 0; mt < 2; mt++) {
        int r = m0 + 32 * wm + 16 * mt + g;
#pragma unroll
        for (int nt = 0; nt < 8; nt++) {
            int col = n0 + 64 * wn + 8 * nt + 2 * t;
            __half h00 = __float2half_rn(acc[mt][nt][0] * scale);
            __half h01 = __float2half_rn(acc[mt][nt][1] * scale);
            __half h10 = __float2half_rn(acc[mt][nt][2] * scale);
            __half h11 = __float2half_rn(acc[mt][nt][3] * scale);
            if (mat == 2) {
                g_Vt[(size_t)col * NTOK + r] = h00;
                g_Vt[(size_t)(col + 1) * NTOK + r] = h01;
                g_Vt[(size_t)col * NTOK + r + 8] = h10;
                g_Vt[(size_t)(col + 1) * NTOK + r + 8] = h11;
            } else {
                __half* dst = (mat == 0) ? g_Qh : g_Kh;
                *(__half2*)&dst[(size_t)r * DHEAD + col] = __halves2half2(h00, h01);
                *(__half2*)&dst[(size_t)(r + 8) * DHEAD + col] = __halves2half2(h10, h11);
            }
        }
    }
}

// ---------------- kernel 2: pipelined fp16 attention with ldmatrix ----------------
// SMEM layout (bytes):
#define SMO_Q   0u        // [128][256] half, row stride 512B, 16B-granule xor swizzle
#define SMO_K0  65536u    // [64][256] half
#define SMO_K1  98304u
#define SMO_V   131072u   // [256][64] half (V^T), row stride 128B
#define SMO_C   163840u   // [128][64] float (cnt), row stride 256B
#define SMO_P   196608u   // [128] rows x 144B, linear
#define SMO_L   215040u   // 256 floats
#define SMEM_DYN (215040u + 1024u)

__global__ __launch_bounds__(256, 1) void attn_kernel(const float* __restrict__ cnt) {
    extern __shared__ char sm[];
    const uint32_t sb = smem_u32(sm);

    const int tid = threadIdx.x, w = tid >> 5, lane = tid & 31;
    const int g = lane >> 2, t = lane & 3;
    const int wm = w & 3, wh = w >> 2;     // 4 m-warps x 2 n/d-half warps
    const int m0 = blockIdx.x * BM;
    const int sp = blockIdx.y;
    const int jb0 = sp * (NTOK / NSPLIT);

    // ldmatrix lane decomposition
    const int lr = lane & 7;               // row-in-8x8
    const int lm = (lane >> 3) & 1;
    const int lh = lane >> 4;

    // A-type rows (Q, P): lanes 0-15 row-blocks, lanes 16-31 k-block +1
    const int ar0 = 32 * wm + lr + 8 * lm;
    const uint32_t qb0 = sb + SMO_Q + (uint32_t)ar0 * 512u;
    const uint32_t qb1 = qb0 + 16u * 512u;
    const uint32_t pb0 = sb + SMO_P + (uint32_t)ar0 * 144u;
    const uint32_t pb1 = pb0 + 16u * 144u;
    // B-type rows (K, V): lanes 0-15 k-block, lanes 16-31 row +8
    const int bnr = lr + 8 * lh;
    const uint32_t kroff = (uint32_t)(32 * wh + bnr) * 512u;
    const uint32_t vb = sb + SMO_V + (uint32_t)(128 * wh + bnr) * 128u;

    // ---- prologue: Q tile + K_0 via cp.async (group 0) ----
#pragma unroll
    for (int i = 0; i < 16; i++) {
        int e = tid + 256 * i;
        int r = e >> 5, blk = e & 31;
        uint32_t d = sb + SMO_Q + (uint32_t)r * 512u + (uint32_t)((blk ^ (r & 7)) << 4);
        cp16(d, &g_Qh[(size_t)(m0 + r) * DHEAD + 8 * blk]);
    }
#pragma unroll
    for (int i = 0; i < 8; i++) {
        int e = tid + 256 * i;
        int r = e >> 5, blk = e & 31;
        uint32_t d = sb + SMO_K0 + (uint32_t)r * 512u + (uint32_t)((blk ^ (r & 7)) << 4);
        cp16(d, &g_Kh[(size_t)(jb0 + r) * DHEAD + 8 * blk]);
    }
    CP_COMMIT();

    float O[2][16][4];
#pragma unroll
    for (int mt = 0; mt < 2; mt++)
#pragma unroll
        for (int nt = 0; nt < 16; nt++)
#pragma unroll
            for (int q = 0; q < 4; q++) O[mt][nt][q] = 0.f;
    float lA[2] = {0.f, 0.f}, lB[2] = {0.f, 0.f};

    const int rA0 = 32 * wm + g, rB0 = rA0 + 8;

    for (int j = 0; j < JBLOCKS; j++) {
        const int jb = jb0 + j * BN;
        __syncthreads();   // prev AV done with V/P/C; K[(j+1)&1] free

        // ---- issue V_j + C_j (one group) ----
#pragma unroll
        for (int i = 0; i < 8; i++) {
            int e = tid + 256 * i;
            int dd = e >> 3, blk = e & 7;
            uint32_t d = sb + SMO_V + (uint32_t)dd * 128u + (uint32_t)((blk ^ (dd & 7)) << 4);
            cp16(d, &g_Vt[(size_t)dd * NTOK + jb + 8 * blk]);
        }
#pragma unroll
        for (int i = 0; i < 8; i++) {
            int e = tid + 256 * i;
            int r = e >> 4, blk = e & 15;
            uint32_t d = sb + SMO_C + (uint32_t)r * 256u +
                         (uint32_t)(((4 * blk) ^ ((r & 7) << 2)) << 2);
            cp16(d, &cnt[(size_t)(m0 + r) * NTOK + jb + 4 * blk]);
        }
        CP_COMMIT();

        // ---- issue K_{j+1} (own group; empty group on last iter) ----
        if (j + 1 < JBLOCKS) {
            uint32_t kb = ((j + 1) & 1) ? SMO_K1 : SMO_K0;
#pragma unroll
            for (int i = 0; i < 8; i++) {
                int e = tid + 256 * i;
                int r = e >> 5, blk = e & 31;
                uint32_t d = sb + kb + (uint32_t)r * 512u + (uint32_t)((blk ^ (r & 7)) << 4);
                cp16(d, &g_Kh[(size_t)(jb + BN + r) * DHEAD + 8 * blk]);
            }
        }
        CP_COMMIT();

        CP_WAIT(2);        // K_j (and Q on j=0) complete
        __syncthreads();

        // ---- QK_j : warp computes S[32 rows x 32 cols], k = 256 via ldmatrix ----
        const uint32_t kbuf = sb + ((j & 1) ? SMO_K1 : SMO_K0) + kroff;
        float S[2][4][4];
#pragma unroll
        for (int mt = 0; mt < 2; mt++)
#pragma unroll
            for (int nt = 0; nt < 4; nt++)
#pragma unroll
                for (int q = 0; q < 4; q++) S[mt][nt][q] = 0.f;

#pragma unroll 4
        for (int s = 0; s < 16; s++) {
            const uint32_t xa = (uint32_t)(((2 * s + lh) ^ lr) << 4);
            const uint32_t xb = (uint32_t)(((2 * s + lm) ^ lr) << 4);
            unsigned a0[4], a1[4], b0[4], b1[4];
            ldsm4(a0[0], a0[1], a0[2], a0[3], qb0 + xa);
            ldsm4(a1[0], a1[1], a1[2], a1[3], qb1 + xa);
            ldsm4(b0[0], b0[1], b0[2], b0[3], kbuf + xb);
            ldsm4(b1[0], b1[1], b1[2], b1[3], kbuf + 16u * 512u + xb);
            mma_f16(S[0][0][0], S[0][0][1], S[0][0][2], S[0][0][3], a0[0], a0[1], a0[2], a0[3], b0[0], b0[1]);
            mma_f16(S[0][1][0], S[0][1][1], S[0][1][2], S[0][1][3], a0[0], a0[1], a0[2], a0[3], b0[2], b0[3]);
            mma_f16(S[0][2][0], S[0][2][1], S[0][2][2], S[0][2][3], a0[0], a0[1], a0[2], a0[3], b1[0], b1[1]);
            mma_f16(S[0][3][0], S[0][3][1], S[0][3][2], S[0][3][3], a0[0], a0[1], a0[2], a0[3], b1[2], b1[3]);
            mma_f16(S[1][0][0], S[1][0][1], S[1][0][2], S[1][0][3], a1[0], a1[1], a1[2], a1[3], b0[0], b0[1]);
            mma_f16(S[1][1][0], S[1][1][1], S[1][1][2], S[1][1][3], a1[0], a1[1], a1[2], a1[3], b0[2], b0[3]);
            mma_f16(S[1][2][0], S[1][2][1], S[1][2][2], S[1][2][3], a1[0], a1[1], a1[2], a1[3], b1[0], b1[1]);
            mma_f16(S[1][3][0], S[1][3][1], S[1][3][2], S[1][3][3], a1[0], a1[1], a1[2], a1[3], b1[2], b1[3]);
        }

        CP_WAIT(1);        // V_j + C_j complete (K_{j+1} may still fly)
        __syncthreads();

        // ---- epilogue: P = exp(S) * cnt -> Ps (fp16), accumulate l ----
        const char* Cs = sm + SMO_C;
        char* Ps = sm + SMO_P;
#pragma unroll
        for (int mt = 0; mt < 2; mt++) {
            int rA = rA0 + 16 * mt, rB = rB0 + 16 * mt;
            float sA = 0.f, sB = 0.f;
#pragma unroll
            for (int nt = 0; nt < 4; nt++) {
                int ci = ((32 * wh + 8 * nt + 2 * t) ^ (g << 2)) << 2;
                float2 cA = *(const float2*)(Cs + rA * 256 + ci);
                float2 cB = *(const float2*)(Cs + rB * 256 + ci);
                float p0 = __expf(S[mt][nt][0]) * cA.x;
                float p1 = __expf(S[mt][nt][1]) * cA.y;
                float p2 = __expf(S[mt][nt][2]) * cB.x;
                float p3 = __expf(S[mt][nt][3]) * cB.y;
                sA += p0 + p1;
                sB += p2 + p3;
                int q = (16 * wh + 4 * nt + t) << 2;
                *(__half2*)(Ps + rA * 144 + q) = __halves2half2(__float2half_rn(p0), __float2half_rn(p1));
                *(__half2*)(Ps + rB * 144 + q) = __halves2half2(__float2half_rn(p2), __float2half_rn(p3));
            }
            sA += __shfl_xor_sync(0xffffffffu, sA, 1);
            sA += __shfl_xor_sync(0xffffffffu, sA, 2);
            sB += __shfl_xor_sync(0xffffffffu, sB, 1);
            sB += __shfl_xor_sync(0xffffffffu, sB, 2);
            lA[mt] += sA;
            lB[mt] += sB;
        }
        __syncthreads();   // P visible to all warps

        // ---- AV_j : O[32 rows x 128 cols] += P @ V^T, k = 64 via ldmatrix ----
#pragma unroll
        for (int s = 0; s < 4; s++) {
            const uint32_t xp = (uint32_t)((2 * s + lh) << 4);
            const uint32_t xv = (uint32_t)(((2 * s + lm) ^ lr) << 4);
            unsigned pa0[4], pa1[4];
            ldsm4(pa0[0], pa0[1], pa0[2], pa0[3], pb0 + xp);
            ldsm4(pa1[0], pa1[1], pa1[2], pa1[3], pb1 + xp);
#pragma unroll
            for (int p = 0; p < 8; p++) {
                unsigned vv[4];
                ldsm4(vv[0], vv[1], vv[2], vv[3], vb + (uint32_t)p * 2048u + xv);
                mma_f16(O[0][2 * p][0], O[0][2 * p][1], O[0][2 * p][2], O[0][2 * p][3],
                        pa0[0], pa0[1], pa0[2], pa0[3], vv[0], vv[1]);
                mma_f16(O[0][2 * p + 1][0], O[0][2 * p + 1][1], O[0][2 * p + 1][2], O[0][2 * p + 1][3],
                        pa0[0], pa0[1], pa0[2], pa0[3], vv[2], vv[3]);
                mma_f16(O[1][2 * p][0], O[1][2 * p][1], O[1][2 * p][2], O[1][2 * p][3],
                        pa1[0], pa1[1], pa1[2], pa1[3], vv[0], vv[1]);
                mma_f16(O[1][2 * p + 1][0], O[1][2 * p + 1][1], O[1][2 * p + 1][2], O[1][2 * p + 1][3],
                        pa1[0], pa1[1], pa1[2], pa1[3], vv[2], vv[3]);
            }
        }
    }

    // ---- O writeout ----
#pragma unroll
    for (int mt = 0; mt < 2; mt++) {
        int rA = m0 + rA0 + 16 * mt, rB = m0 + rB0 + 16 * mt;
#pragma unroll
        for (int nt = 0; nt < 16; nt++) {
            int col = 128 * wh + 8 * nt + 2 * t;
            *(float2*)&g_Op[sp][rA][col] = make_float2(O[mt][nt][0], O[mt][nt][1]);
            *(float2*)&g_Op[sp][rB][col] = make_float2(O[mt][nt][2], O[mt][nt][3]);
        }
    }

    // ---- l reduce across the two wh warps ----
    float* Lr = (float*)(sm + SMO_L);
    if (t == 0) {
#pragma unroll
        for (int mt = 0; mt < 2; mt++) {
            Lr[wh * 128 + rA0 + 16 * mt] = lA[mt];
            Lr[wh * 128 + rB0 + 16 * mt] = lB[mt];
        }
    }
    __syncthreads();
    if (tid < 128) g_ls[sp][m0 + tid] = Lr[tid] + Lr[128 + tid];
}

// ---------------- kernel 3: combine + ELU ----------------
__global__ __launch_bounds__(256) void combine_kernel(float* __restrict__ out) {
    const int i = blockIdx.x;
    const int d = threadIdx.x;
    float den = g_ls[0][i] + g_ls[1][i];
    float num = g_Op[0][i][d] + g_Op[1][i][d];
    float r = num / den;
    out[(size_t)i * DHEAD + d] = (r > 0.f) ? r : expm1f(r);
}

// ---------------- launch ----------------
extern "C" void kernel_launch(void* const* d_in, const int* in_sizes, int n_in,
                              void* d_out, int out_size) {
    (void)in_sizes; (void)n_in; (void)out_size;
    const float* feat = (const float*)d_in[0];
    const float* cnt = (const float*)d_in[1];
    const float* Wq = (const float*)d_in[2];
    const float* Wk = (const float*)d_in[3];
    const float* Wv = (const float*)d_in[4];

    proj_kernel<<<dim3(NTOK / 128, DHEAD / 128, 3), 256>>>(feat, Wq, Wk, Wv);

    cudaFuncSetAttribute(attn_kernel, cudaFuncAttributeMaxDynamicSharedMemorySize, (int)SMEM_DYN);
    attn_kernel<<<dim3(NTOK / BM, NSPLIT), 256, SMEM_DYN>>>(cnt);

    combine_kernel<<<NTOK, 256>>>((float*)d_out);
}